// round 1
// baseline (speedup 1.0000x reference)
#include <cuda_runtime.h>
#include <math.h>

#define H   128
#define Lc  4
#define NT  4096
#define Mm  4
#define Ss  16384
#define Kk  12
#define SKc (Ss*Kk)          // 196608
#define EIc (Ss*(Kk-1))      // 180224
#define ECc (NT*8)           // 32768
#define Bc  64

// ---------------- device scratch (static, no allocation) ----------------
__device__ float g_h   [SKc*H];
__device__ float g_t1  [SKc*H];
__device__ float g_t2  [SKc*H];
__device__ float g_t3  [SKc*H];
__device__ float g_r   [Ss*H];
__device__ float g_h2  [Ss*H];
__device__ float g_o   [Ss*H];
__device__ float g_qkv [Ss*3*H];
__device__ float g_hcan[NT*H];
__device__ float g_agg2[NT*H];
__device__ float g_c1  [NT*H];
__device__ float g_c2  [NT*H];
__device__ float g_cnt [NT];
__device__ int   g_slot[Ss];
__device__ int   g_slotcnt[NT];
__device__ float g_linE0[8*H];
__device__ float g_linE1[8*H];
__device__ float g_stats[2*H];

// ---------------- init: h = (atom + dist_pe + relu(logp*W+b)) * valid ----
__global__ void k_init(const int* __restrict__ atom_ids, const int* __restrict__ node_ids,
                       const float* __restrict__ log_probs, const float* __restrict__ atom_tab,
                       const float* __restrict__ dist_tab, const float* __restrict__ logp_W,
                       const float* __restrict__ logp_b)
{
    int idx = blockIdx.x*blockDim.x + threadIdx.x;
    int i = idx >> 7, c = idx & 127;
    int nid = node_ids[i];
    float valid = nid >= 0 ? 1.f : 0.f;
    int cl = nid > 0 ? nid : 0;
    int aid = atom_ids[cl];
    int j = i % Kk;                       // BFS distance == chain position
    float x = atom_tab[aid*H + c] + dist_tab[j*H + c];
    float pe = fmaxf(log_probs[i/Kk]*logp_W[c] + logp_b[c], 0.f);
    g_h[idx] = (x + pe)*valid;
}

// counts per canonical node + stable-enough slot assignment (perm.-invariant downstream)
__global__ void k_cntslot(const int* __restrict__ node_ids)
{
    int s = blockIdx.x*blockDim.x + threadIdx.x;
    if (s >= Ss) return;
    int r = node_ids[s*Kk];
    g_slot[s] = atomicAdd(&g_slotcnt[r], 1);
    atomicAdd(&g_cnt[r], 1.f);
}

// linE[r,c] = b[c] + bond_tab[r,:] . W[c,:]   (8 x 128)
__global__ void k_linE(const float* __restrict__ bond_tab, const float* __restrict__ W,
                       const float* __restrict__ b, float* __restrict__ out)
{
    int t = blockIdx.x*blockDim.x + threadIdx.x;
    if (t >= 8*H) return;
    int r = t >> 7, c = t & 127;
    float s = b[c];
    #pragma unroll 16
    for (int k = 0; k < H; k++) s += bond_tab[r*H+k]*W[c*H+k];
    out[t] = s;
}

// hh = (1+eps)*h + chain-agg(relu(h[src] + linE0[bond]))
__global__ void k_hh_intra(const int* __restrict__ isrc, const int* __restrict__ ibond,
                           const float* __restrict__ epsp)
{
    int idx = blockIdx.x*blockDim.x + threadIdx.x;
    int i = idx >> 7, c = idx & 127;
    float v = (1.f + *epsp)*g_h[idx];
    int j = i % Kk;
    if (j > 0) {
        int e = (i/Kk)*(Kk-1) + j - 1;            // unique edge into i
        int s = isrc[e];
        v += fmaxf(g_h[s*H + c] + g_linE0[ibond[e]*H + c], 0.f);
    }
    g_t1[idx] = v;
}

// ---------------- generic 128-wide GEMM: C = act(A@W^T + bias [+ res]) ----
__global__ void __launch_bounds__(256)
k_gemm(const float* __restrict__ A, long lda,
       const float* __restrict__ W, const float* __restrict__ bias,
       const float* __restrict__ res, long ldres,
       float* __restrict__ C, long ldc, int act)
{
    __shared__ float As[128][33];
    __shared__ float Ws[128][33];
    int tid = threadIdx.x;
    int tx = tid & 15, ty = tid >> 4;
    long row0 = (long)blockIdx.x * 128;
    const float* Ablk = A + row0*lda;
    float acc[8][8];
    #pragma unroll
    for (int r = 0; r < 8; r++)
        #pragma unroll
        for (int c = 0; c < 8; c++) acc[r][c] = 0.f;

    for (int k0 = 0; k0 < 128; k0 += 32) {
        #pragma unroll
        for (int t = 0; t < 16; t++) {
            int lin = t*256 + tid;
            int r = lin >> 5, kk = lin & 31;
            As[r][kk] = Ablk[(long)r*lda + k0 + kk];
            Ws[r][kk] = W[r*128 + k0 + kk];
        }
        __syncthreads();
        #pragma unroll
        for (int kk = 0; kk < 32; kk++) {
            float a[8], w[8];
            #pragma unroll
            for (int r = 0; r < 8; r++) a[r] = As[ty*8+r][kk];
            #pragma unroll
            for (int c = 0; c < 8; c++) w[c] = Ws[tx + 16*c][kk];
            #pragma unroll
            for (int r = 0; r < 8; r++)
                #pragma unroll
                for (int c = 0; c < 8; c++)
                    acc[r][c] += a[r]*w[c];
        }
        __syncthreads();
    }
    #pragma unroll
    for (int r = 0; r < 8; r++) {
        long row = row0 + ty*8 + r;
        #pragma unroll
        for (int c = 0; c < 8; c++) {
            int col = tx + 16*c;
            float v = acc[r][c] + bias[col];
            if (res) v += res[row*ldres + col];
            if (act) v = fmaxf(v, 0.f);
            C[row*ldc + col] = v;
        }
    }
}

// ---------------- BatchNorm: column stats + apply ----------------
__global__ void k_bn_stats(const float* __restrict__ X)
{
    int c = threadIdx.x;                  // 128 threads
    long r0 = (long)blockIdx.x * 512;
    float s = 0.f, s2 = 0.f;
    for (int r = 0; r < 512; r++) {
        float v = X[(r0 + r)*H + c];
        s += v; s2 += v*v;
    }
    atomicAdd(&g_stats[c], s);
    atomicAdd(&g_stats[H + c], s2);
}

__global__ void k_bn_apply(const float* __restrict__ X, float* __restrict__ Y,
                           const float* __restrict__ gamma, const float* __restrict__ beta,
                           const int* __restrict__ nids, float invn)
{
    int idx = blockIdx.x*blockDim.x + threadIdx.x;
    int row = idx >> 7, c = idx & 127;
    float mu = g_stats[c]*invn;
    float var = g_stats[H + c]*invn - mu*mu;
    float v = (X[idx] - mu)*rsqrtf(var + 1e-5f)*gamma[c] + beta[c];
    if (nids && nids[row] < 0) v = 0.f;
    Y[idx] = v;
}

// ---------------- canonical graph path ----------------
__global__ void k_hcan_acc(const int* __restrict__ node_ids)
{
    int idx = blockIdx.x*blockDim.x + threadIdx.x;     // Ss*H
    int s = idx >> 7, c = idx & 127;
    int r = node_ids[s*Kk];
    atomicAdd(&g_hcan[r*H + c], g_h[(s*Kk)*H + c]);
}

__global__ void k_hcan_div()
{
    int idx = blockIdx.x*blockDim.x + threadIdx.x;     // NT*H
    g_hcan[idx] *= 1.f/fmaxf(g_cnt[idx >> 7], 1.f);
}

__global__ void k_cagg(const int* __restrict__ eidx, const int* __restrict__ cb)
{
    int idx = blockIdx.x*blockDim.x + threadIdx.x;     // ECc*H
    int e = idx >> 7, c = idx & 127;
    int sN = eidx[e], dN = eidx[ECc + e];
    float m = fmaxf(g_hcan[sN*H + c] + g_linE1[cb[e]*H + c], 0.f);
    atomicAdd(&g_agg2[dN*H + c], m);
}

__global__ void k_hh2(const float* __restrict__ epsp)
{
    int idx = blockIdx.x*blockDim.x + threadIdx.x;     // NT*H
    g_c1[idx] = (1.f + *epsp)*g_hcan[idx] + g_agg2[idx];
}

// h_new = valid ? relu(h1n + (root ? hintn[nid] : h_nr)) : 0
__global__ void k_combine(const int* __restrict__ node_ids)
{
    int idx = blockIdx.x*blockDim.x + threadIdx.x;     // SKc*H
    int i = idx >> 7, c = idx & 127;
    int nid = node_ids[i];
    float outv = 0.f;
    if (nid >= 0) {
        float v = g_t2[idx];                            // h1 (post-BN)
        if (i % Kk == 0) v += g_c2[nid*H + c];          // root: inter-graph term
        else             v += g_t3[idx] + g_r[(i/Kk)*H + c];   // non-root
        outv = fmaxf(v, 0.f);
    }
    g_h[idx] = outv;
}

// ---------------- pooling + MHA + readout ----------------
__global__ void k_pool(const int* __restrict__ node_ids)
{
    int idx = blockIdx.x*blockDim.x + threadIdx.x;     // Ss*H
    int s = idx >> 7, c = idx & 127;
    float a = 0.f;
    #pragma unroll
    for (int j = 0; j < Kk; j++) a += g_h[(s*Kk + j)*H + c];
    int r = node_ids[s*Kk];
    g_h2[(r*Mm + g_slot[s])*H + c] = a;
}

__global__ void k_attn()
{
    int t = blockIdx.x*blockDim.x + threadIdx.x;       // NT*4*4 = 65536
    int q = t & 3, hh = (t >> 2) & 3, n = t >> 4;
    const float scale = rsqrtf(32.f);
    const float* base = g_qkv + (long)(n*Mm)*384;
    float qv[32];
    #pragma unroll
    for (int d = 0; d < 32; d++) qv[d] = base[q*384 + hh*32 + d];
    float sc[4];
    #pragma unroll
    for (int k = 0; k < 4; k++) {
        const float* kr = base + k*384 + 128 + hh*32;
        float s = 0.f;
        #pragma unroll
        for (int d = 0; d < 32; d++) s += qv[d]*kr[d];
        sc[k] = s*scale;
    }
    float mx = fmaxf(fmaxf(sc[0], sc[1]), fmaxf(sc[2], sc[3]));
    float ss = 0.f;
    #pragma unroll
    for (int k = 0; k < 4; k++) { sc[k] = expf(sc[k] - mx); ss += sc[k]; }
    float inv = 1.f/ss;
    float ov[32];
    #pragma unroll
    for (int d = 0; d < 32; d++) ov[d] = 0.f;
    #pragma unroll
    for (int k = 0; k < 4; k++) {
        float p = sc[k]*inv;
        const float* vr = base + k*384 + 256 + hh*32;
        #pragma unroll
        for (int d = 0; d < 32; d++) ov[d] += p*vr[d];
    }
    float* ob = g_o + ((long)n*Mm + q)*H + hh*32;
    #pragma unroll
    for (int d = 0; d < 32; d++) ob[d] = ov[d];
}

__global__ void k_mean4()
{
    int idx = blockIdx.x*blockDim.x + threadIdx.x;     // NT*H
    int n = idx >> 7, c = idx & 127;
    long b = (long)n*Mm*H + c;
    g_c1[idx] = 0.25f*(g_r[b] + g_r[b + H] + g_r[b + 2*H] + g_r[b + 3*H]);
}

__global__ void k_final(const int* __restrict__ batch, const float* __restrict__ gamma,
                        const float* __restrict__ beta, float* __restrict__ out)
{
    int idx = blockIdx.x*blockDim.x + threadIdx.x;     // NT*H
    int n = idx >> 7, c = idx & 127;
    const float invn = 1.f/NT;
    float mu = g_stats[c]*invn;
    float var = g_stats[H + c]*invn - mu*mu;
    float v = (g_c1[idx] - mu)*rsqrtf(var + 1e-5f)*gamma[c] + beta[c];
    atomicAdd(&out[batch[n]*H + c], v);
}

// ---------------- host orchestration ----------------
extern "C" void kernel_launch(void* const* d_in, const int* in_sizes, int n_in,
                              void* d_out, int out_size)
{
    const int*   atom_ids   = (const int*)  d_in[0];
    const int*   node_ids   = (const int*)  d_in[1];
    const int*   intra_ei   = (const int*)  d_in[2];
    const int*   intra_bond = (const int*)  d_in[3];
    const int*   edge_index = (const int*)  d_in[4];
    const int*   canon_bond = (const int*)  d_in[5];
    const int*   batch      = (const int*)  d_in[6];
    const float* log_probs  = (const float*)d_in[7];
    const float* atom_tab   = (const float*)d_in[8];
    const float* bond_tab   = (const float*)d_in[9];
    const float* dist_tab   = (const float*)d_in[10];
    const float* logp_W     = (const float*)d_in[11];
    const float* logp_b     = (const float*)d_in[12];
    const float* lw         = (const float*)d_in[13];
    const float* lb         = (const float*)d_in[14];
    const float* bn_g       = (const float*)d_in[15];
    const float* bn_b       = (const float*)d_in[16];
    const float* eps        = (const float*)d_in[17];
    const float* inW        = (const float*)d_in[18];
    const float* inB        = (const float*)d_in[19];
    const float* outW       = (const float*)d_in[20];
    const float* outB       = (const float*)d_in[21];
    const float* ro_g       = (const float*)d_in[22];
    const float* ro_b       = (const float*)d_in[23];
    float* out = (float*)d_out;

    float *p_h, *p_t1, *p_t2, *p_t3, *p_r, *p_h2, *p_o, *p_qkv, *p_hcan, *p_agg2,
          *p_c1, *p_c2, *p_stats, *p_cnt, *p_linE0, *p_linE1;
    int *p_slotcnt;
    cudaGetSymbolAddress((void**)&p_h,    g_h);
    cudaGetSymbolAddress((void**)&p_t1,   g_t1);
    cudaGetSymbolAddress((void**)&p_t2,   g_t2);
    cudaGetSymbolAddress((void**)&p_t3,   g_t3);
    cudaGetSymbolAddress((void**)&p_r,    g_r);
    cudaGetSymbolAddress((void**)&p_h2,   g_h2);
    cudaGetSymbolAddress((void**)&p_o,    g_o);
    cudaGetSymbolAddress((void**)&p_qkv,  g_qkv);
    cudaGetSymbolAddress((void**)&p_hcan, g_hcan);
    cudaGetSymbolAddress((void**)&p_agg2, g_agg2);
    cudaGetSymbolAddress((void**)&p_c1,   g_c1);
    cudaGetSymbolAddress((void**)&p_c2,   g_c2);
    cudaGetSymbolAddress((void**)&p_stats,g_stats);
    cudaGetSymbolAddress((void**)&p_cnt,  g_cnt);
    cudaGetSymbolAddress((void**)&p_linE0,g_linE0);
    cudaGetSymbolAddress((void**)&p_linE1,g_linE1);
    cudaGetSymbolAddress((void**)&p_slotcnt, g_slotcnt);

    const int* isrc = intra_ei;     // first EIc entries = src

    cudaMemsetAsync(p_cnt, 0, NT*sizeof(float));
    cudaMemsetAsync(p_slotcnt, 0, NT*sizeof(int));
    k_init<<<SKc*H/256, 256>>>(atom_ids, node_ids, log_probs, atom_tab, dist_tab, logp_W, logp_b);
    k_cntslot<<<Ss/256, 256>>>(node_ids);

    for (int l = 0; l < Lc; l++) {
        const float* W  = lw + (long)l*8*H*H;
        const float* bb = lb + (long)l*8*H;
        k_linE<<<4, 256>>>(bond_tab, W + 0*H*H, bb + 0*H, p_linE0);
        k_linE<<<4, 256>>>(bond_tab, W + 5*H*H, bb + 5*H, p_linE1);

        // intra GINE
        k_hh_intra<<<SKc*H/256, 256>>>(isrc, intra_bond, eps + l*2);
        k_gemm<<<SKc/128, 256>>>(p_t1, 128, W + 1*H*H, bb + 1*H, nullptr, 0, p_t2, 128, 1);
        k_gemm<<<SKc/128, 256>>>(p_t2, 128, W + 2*H*H, bb + 2*H, nullptr, 0, p_t1, 128, 0);
        cudaMemsetAsync(p_stats, 0, 2*H*sizeof(float));
        k_bn_stats<<<SKc/512, 128>>>(p_t1);
        k_bn_apply<<<SKc*H/256, 256>>>(p_t1, p_t2, bn_g + (l*2+0)*H, bn_b + (l*2+0)*H, node_ids, 1.f/SKc);

        // non-root path: h@W3 + h_root@W4
        k_gemm<<<SKc/128, 256>>>(p_h, 128,    W + 3*H*H, bb + 3*H, nullptr, 0, p_t3, 128, 0);
        k_gemm<<<Ss/128, 256>>>(p_h, Kk*H,    W + 4*H*H, bb + 4*H, nullptr, 0, p_r,  128, 0);

        // canonical graph
        cudaMemsetAsync(p_hcan, 0, NT*H*sizeof(float));
        k_hcan_acc<<<Ss*H/256, 256>>>(node_ids);
        k_hcan_div<<<NT*H/256, 256>>>();
        cudaMemsetAsync(p_agg2, 0, NT*H*sizeof(float));
        k_cagg<<<ECc*H/256, 256>>>(edge_index, canon_bond);
        k_hh2<<<NT*H/256, 256>>>(eps + l*2 + 1);
        k_gemm<<<NT/128, 256>>>(p_c1, 128, W + 6*H*H, bb + 6*H, nullptr, 0, p_c2, 128, 1);
        k_gemm<<<NT/128, 256>>>(p_c2, 128, W + 7*H*H, bb + 7*H, nullptr, 0, p_c1, 128, 0);
        cudaMemsetAsync(p_stats, 0, 2*H*sizeof(float));
        k_bn_stats<<<NT/512, 128>>>(p_c1);
        k_bn_apply<<<NT*H/256, 256>>>(p_c1, p_c2, bn_g + (l*2+1)*H, bn_b + (l*2+1)*H, nullptr, 1.f/NT);

        k_combine<<<SKc*H/256, 256>>>(node_ids);
    }

    // pooling + attention + readout
    k_pool<<<Ss*H/256, 256>>>(node_ids);
    for (int cb = 0; cb < 3; cb++)
        k_gemm<<<Ss/128, 256>>>(p_h2, 128, inW + (long)cb*H*H, inB + cb*H, nullptr, 0,
                                p_qkv + cb*H, 384, 0);
    k_attn<<<NT*16/256, 256>>>();
    k_gemm<<<Ss/128, 256>>>(p_o, 128, outW, outB, p_h2, 128, p_r, 128, 0);
    k_mean4<<<NT*H/256, 256>>>();
    cudaMemsetAsync(p_stats, 0, 2*H*sizeof(float));
    k_bn_stats<<<NT/512, 128>>>(p_c1);
    cudaMemsetAsync(d_out, 0, (size_t)out_size*sizeof(float));
    k_final<<<NT*H/256, 256>>>(batch, ro_g, ro_b, out);
}

// round 2
// speedup vs baseline: 1.6917x; 1.6917x over previous
#include <cuda_runtime.h>
#include <cuda_bf16.h>
#include <math.h>
#include <stdint.h>

#define H   128
#define Lc  4
#define NT  4096
#define Mm  4
#define Ss  16384
#define Kk  12
#define SKc (Ss*Kk)
#define EIc (Ss*(Kk-1))
#define ECc (NT*8)
#define Bc  64

__device__ float g_h   [SKc*H];
__device__ float g_t1  [SKc*H];
__device__ float g_t2  [SKc*H];
__device__ float g_t3  [SKc*H];
__device__ float g_r   [Ss*H];
__device__ float g_h2  [Ss*H];
__device__ float g_o   [Ss*H];
__device__ float g_qkv [Ss*3*H];
__device__ float g_hcan[NT*H];
__device__ float g_agg2[NT*H];
__device__ float g_c1  [NT*H];
__device__ float g_c2  [NT*H];
__device__ float g_cnt [NT];
__device__ int   g_slot[Ss];
__device__ int   g_slotcnt[NT];
__device__ float g_linE0[8*H];
__device__ float g_linE1[8*H];
__device__ float g_stats [2*H];
__device__ float g_stats2[2*H];

__global__ void k_init(const int* __restrict__ atom_ids, const int* __restrict__ node_ids,
                       const float* __restrict__ log_probs, const float* __restrict__ atom_tab,
                       const float* __restrict__ dist_tab, const float* __restrict__ logp_W,
                       const float* __restrict__ logp_b)
{
    int idx = blockIdx.x*blockDim.x + threadIdx.x;
    int i = idx >> 7, c = idx & 127;
    int nid = node_ids[i];
    float valid = nid >= 0 ? 1.f : 0.f;
    int cl = nid > 0 ? nid : 0;
    int aid = atom_ids[cl];
    int j = i % Kk;
    float x = atom_tab[aid*H + c] + dist_tab[j*H + c];
    float pe = fmaxf(log_probs[i/Kk]*logp_W[c] + logp_b[c], 0.f);
    g_h[idx] = (x + pe)*valid;
}

__global__ void k_cntslot(const int* __restrict__ node_ids)
{
    int s = blockIdx.x*blockDim.x + threadIdx.x;
    if (s >= Ss) return;
    int r = node_ids[s*Kk];
    g_slot[s] = atomicAdd(&g_slotcnt[r], 1);
    atomicAdd(&g_cnt[r], 1.f);
}

__global__ void k_linE(const float* __restrict__ bond_tab, const float* __restrict__ W,
                       const float* __restrict__ b, float* __restrict__ out)
{
    int t = blockIdx.x*blockDim.x + threadIdx.x;
    if (t >= 8*H) return;
    int r = t >> 7, c = t & 127;
    float s = b[c];
    #pragma unroll 16
    for (int k = 0; k < H; k++) s += bond_tab[r*H+k]*W[c*H+k];
    out[t] = s;
}

__global__ void k_hh_intra(const int* __restrict__ isrc, const int* __restrict__ ibond,
                           const float* __restrict__ epsp)
{
    int idx = blockIdx.x*blockDim.x + threadIdx.x;
    int i = idx >> 7, c = idx & 127;
    float v = (1.f + *epsp)*g_h[idx];
    int j = i % Kk;
    if (j > 0) {
        int e = (i/Kk)*(Kk-1) + j - 1;
        int s = isrc[e];
        v += fmaxf(g_h[s*H + c] + g_linE0[ibond[e]*H + c], 0.f);
    }
    g_t1[idx] = v;
}

// ============ tensor-core GEMM: bf16 3-term split (~fp32 accuracy) ============
#define A_TILE_W 132
#define B_TILE_W 66
#define SA_WORDS (8*4*A_TILE_W)
#define SB_WORDS (16*4*B_TILE_W)
#define GEMM_SMEM_BYTES ((2*SA_WORDS + 2*SB_WORDS)*4)

#define MMA_BF16(d, a, b0, b1) \
  asm volatile("mma.sync.aligned.m16n8k16.row.col.f32.bf16.bf16.f32 " \
    "{%0,%1,%2,%3}, {%4,%5,%6,%7}, {%8,%9}, {%0,%1,%2,%3};" \
    : "+f"(d[0]), "+f"(d[1]), "+f"(d[2]), "+f"(d[3]) \
    : "r"(a.x), "r"(a.y), "r"(a.z), "r"(a.w), "r"(b0), "r"(b1))

__device__ __forceinline__ void split_pack(float x, float y, uint32_t& wh, uint32_t& wl)
{
    __nv_bfloat16 h0 = __float2bfloat16_rn(x);
    __nv_bfloat16 h1 = __float2bfloat16_rn(y);
    __nv_bfloat16 l0 = __float2bfloat16_rn(x - __bfloat162float(h0));
    __nv_bfloat16 l1 = __float2bfloat16_rn(y - __bfloat162float(h1));
    wh = (uint32_t)__bfloat16_as_ushort(h0) | ((uint32_t)__bfloat16_as_ushort(h1) << 16);
    wl = (uint32_t)__bfloat16_as_ushort(l0) | ((uint32_t)__bfloat16_as_ushort(l1) << 16);
}

__global__ void __launch_bounds__(256, 2)
k_gemm_tc(const float* __restrict__ A, long lda,
          const float* __restrict__ W,
          const float* __restrict__ bias,
          const float* __restrict__ res, long ldres,
          float* __restrict__ C, long ldc, int act)
{
    extern __shared__ uint32_t sm[];
    uint32_t* sAh = sm;
    uint32_t* sAl = sm + SA_WORDS;
    uint32_t* sBh = sm + 2*SA_WORDS;
    uint32_t* sBl = sm + 2*SA_WORDS + SB_WORDS;

    int tid = threadIdx.x;
    int lane = tid & 31, wid = tid >> 5;
    int warp_m = wid & 3, warp_n = wid >> 2;
    long row0 = (long)blockIdx.x * 128;

    float acc[2][8][4];
    #pragma unroll
    for (int mf = 0; mf < 2; mf++)
        #pragma unroll
        for (int nf = 0; nf < 8; nf++)
            #pragma unroll
            for (int q = 0; q < 4; q++) acc[mf][nf][q] = 0.f;

    for (int chunk = 0; chunk < 2; chunk++) {
        if (chunk) __syncthreads();
        #pragma unroll
        for (int it = 0; it < 16; it++) {
            int p = it*256 + tid;
            int r = p >> 5, kp = p & 31;
            float2 v = *(const float2*)(A + (row0 + r)*lda + chunk*64 + kp*2);
            uint32_t wh, wl; split_pack(v.x, v.y, wh, wl);
            int mt = r >> 4, rm = r & 15, g = rm & 7, hir = rm >> 3;
            int kt = kp >> 3, t = kp & 3, khi = (kp >> 2) & 1;
            int addr = (mt*4 + kt)*A_TILE_W + (g*4 + t)*4 + hir + 2*khi;
            sAh[addr] = wh; sAl[addr] = wl;
        }
        #pragma unroll
        for (int it = 0; it < 16; it++) {
            int p = it*256 + tid;
            int n = p >> 5, kp = p & 31;
            float2 v = *(const float2*)(W + n*128 + chunk*64 + kp*2);
            uint32_t wh, wl; split_pack(v.x, v.y, wh, wl);
            int nt = n >> 3, g = n & 7;
            int kt = kp >> 3, t = kp & 3, khi = (kp >> 2) & 1;
            int addr = (nt*4 + kt)*B_TILE_W + (g*4 + t)*2 + khi;
            sBh[addr] = wh; sBl[addr] = wl;
        }
        __syncthreads();

        #pragma unroll
        for (int kt = 0; kt < 4; kt++) {
            uint4 ah[2], al[2];
            #pragma unroll
            for (int mf = 0; mf < 2; mf++) {
                int mt = warp_m*2 + mf;
                int a = (mt*4 + kt)*A_TILE_W + lane*4;
                ah[mf] = *(const uint4*)&sAh[a];
                al[mf] = *(const uint4*)&sAl[a];
            }
            #pragma unroll
            for (int nf = 0; nf < 8; nf++) {
                int nt = warp_n*8 + nf;
                int b = (nt*4 + kt)*B_TILE_W + lane*2;
                uint32_t bh0 = sBh[b], bh1 = sBh[b+1];
                uint32_t bl0 = sBl[b], bl1 = sBl[b+1];
                #pragma unroll
                for (int mf = 0; mf < 2; mf++) {
                    MMA_BF16(acc[mf][nf], ah[mf], bh0, bh1);
                    MMA_BF16(acc[mf][nf], al[mf], bh0, bh1);
                    MMA_BF16(acc[mf][nf], ah[mf], bl0, bl1);
                }
            }
        }
    }

    int g = lane >> 2, t = lane & 3;
    #pragma unroll
    for (int mf = 0; mf < 2; mf++) {
        #pragma unroll
        for (int nf = 0; nf < 8; nf++) {
            int col = warp_n*64 + nf*8 + t*2;
            long r0 = row0 + warp_m*32 + mf*16 + g;
            long r1 = r0 + 8;
            float b0 = bias[col], b1 = bias[col+1];
            float v00 = acc[mf][nf][0] + b0, v01 = acc[mf][nf][1] + b1;
            float v10 = acc[mf][nf][2] + b0, v11 = acc[mf][nf][3] + b1;
            if (res) {
                v00 += res[r0*ldres + col]; v01 += res[r0*ldres + col + 1];
                v10 += res[r1*ldres + col]; v11 += res[r1*ldres + col + 1];
            }
            if (act) {
                v00 = fmaxf(v00, 0.f); v01 = fmaxf(v01, 0.f);
                v10 = fmaxf(v10, 0.f); v11 = fmaxf(v11, 0.f);
            }
            *(float2*)&C[r0*ldc + col] = make_float2(v00, v01);
            *(float2*)&C[r1*ldc + col] = make_float2(v10, v11);
        }
    }
}

// ---------------- BatchNorm ----------------
__global__ void k_bn_stats(const float* __restrict__ X, float* __restrict__ stats)
{
    int c = threadIdx.x;
    long r0 = (long)blockIdx.x * 512;
    float s = 0.f, s2 = 0.f;
    for (int r = 0; r < 512; r++) {
        float v = X[(r0 + r)*H + c];
        s += v; s2 += v*v;
    }
    atomicAdd(&stats[c], s);
    atomicAdd(&stats[H + c], s2);
}

__global__ void k_bn_apply(const float* __restrict__ X, float* __restrict__ Y,
                           const float* __restrict__ stats,
                           const float* __restrict__ gamma, const float* __restrict__ beta,
                           float invn)
{
    int idx = blockIdx.x*blockDim.x + threadIdx.x;
    int c = idx & 127;
    float mu = stats[c]*invn;
    float var = stats[H + c]*invn - mu*mu;
    Y[idx] = (X[idx] - mu)*rsqrtf(var + 1e-5f)*gamma[c] + beta[c];
}

// ---------------- canonical graph path ----------------
__global__ void k_hcan_acc(const int* __restrict__ node_ids)
{
    int idx = blockIdx.x*blockDim.x + threadIdx.x;
    int s = idx >> 7, c = idx & 127;
    int r = node_ids[s*Kk];
    atomicAdd(&g_hcan[r*H + c], g_h[(s*Kk)*H + c]);
}

__global__ void k_hcan_div()
{
    int idx = blockIdx.x*blockDim.x + threadIdx.x;
    g_hcan[idx] *= 1.f/fmaxf(g_cnt[idx >> 7], 1.f);
}

__global__ void k_cagg(const int* __restrict__ eidx, const int* __restrict__ cb)
{
    int idx = blockIdx.x*blockDim.x + threadIdx.x;
    int e = idx >> 7, c = idx & 127;
    int sN = eidx[e], dN = eidx[ECc + e];
    float m = fmaxf(g_hcan[sN*H + c] + g_linE1[cb[e]*H + c], 0.f);
    atomicAdd(&g_agg2[dN*H + c], m);
}

__global__ void k_hh2(const float* __restrict__ epsp)
{
    int idx = blockIdx.x*blockDim.x + threadIdx.x;
    g_c1[idx] = (1.f + *epsp)*g_hcan[idx] + g_agg2[idx];
}

// h_new = valid ? relu( BN(t1) + (root ? c2[nid] : t3 + r_sub) ) : 0
__global__ void k_combine(const int* __restrict__ node_ids,
                          const float* __restrict__ gamma, const float* __restrict__ beta)
{
    int idx = blockIdx.x*blockDim.x + threadIdx.x;
    int i = idx >> 7, c = idx & 127;
    int nid = node_ids[i];
    float outv = 0.f;
    if (nid >= 0) {
        const float invn = 1.f/SKc;
        float mu = g_stats[c]*invn;
        float var = g_stats[H + c]*invn - mu*mu;
        float v = (g_t1[idx] - mu)*rsqrtf(var + 1e-5f)*gamma[c] + beta[c];
        if (i % Kk == 0) v += g_c2[nid*H + c];
        else             v += g_t3[idx] + g_r[(i/Kk)*H + c];
        outv = fmaxf(v, 0.f);
    }
    g_h[idx] = outv;
}

// ---------------- pooling + MHA + readout ----------------
__global__ void k_pool(const int* __restrict__ node_ids)
{
    int idx = blockIdx.x*blockDim.x + threadIdx.x;
    int s = idx >> 7, c = idx & 127;
    float a = 0.f;
    #pragma unroll
    for (int j = 0; j < Kk; j++) a += g_h[(s*Kk + j)*H + c];
    int r = node_ids[s*Kk];
    g_h2[(r*Mm + g_slot[s])*H + c] = a;
}

__global__ void k_attn()
{
    int t = blockIdx.x*blockDim.x + threadIdx.x;
    int q = t & 3, hh = (t >> 2) & 3, n = t >> 4;
    const float scale = rsqrtf(32.f);
    const float* base = g_qkv + (long)(n*Mm)*384;
    float qv[32];
    #pragma unroll
    for (int d = 0; d < 32; d++) qv[d] = base[q*384 + hh*32 + d];
    float sc[4];
    #pragma unroll
    for (int k = 0; k < 4; k++) {
        const float* kr = base + k*384 + 128 + hh*32;
        float s = 0.f;
        #pragma unroll
        for (int d = 0; d < 32; d++) s += qv[d]*kr[d];
        sc[k] = s*scale;
    }
    float mx = fmaxf(fmaxf(sc[0], sc[1]), fmaxf(sc[2], sc[3]));
    float ss = 0.f;
    #pragma unroll
    for (int k = 0; k < 4; k++) { sc[k] = expf(sc[k] - mx); ss += sc[k]; }
    float inv = 1.f/ss;
    float ov[32];
    #pragma unroll
    for (int d = 0; d < 32; d++) ov[d] = 0.f;
    #pragma unroll
    for (int k = 0; k < 4; k++) {
        float p = sc[k]*inv;
        const float* vr = base + k*384 + 256 + hh*32;
        #pragma unroll
        for (int d = 0; d < 32; d++) ov[d] += p*vr[d];
    }
    float* ob = g_o + ((long)n*Mm + q)*H + hh*32;
    #pragma unroll
    for (int d = 0; d < 32; d++) ob[d] = ov[d];
}

__global__ void k_mean4()
{
    int idx = blockIdx.x*blockDim.x + threadIdx.x;
    int n = idx >> 7, c = idx & 127;
    long b = (long)n*Mm*H + c;
    g_c1[idx] = 0.25f*(g_r[b] + g_r[b + H] + g_r[b + 2*H] + g_r[b + 3*H]);
}

__global__ void k_final(const int* __restrict__ batch, const float* __restrict__ gamma,
                        const float* __restrict__ beta, float* __restrict__ out)
{
    int idx = blockIdx.x*blockDim.x + threadIdx.x;
    int n = idx >> 7, c = idx & 127;
    const float invn = 1.f/NT;
    float mu = g_stats[c]*invn;
    float var = g_stats[H + c]*invn - mu*mu;
    float v = (g_c1[idx] - mu)*rsqrtf(var + 1e-5f)*gamma[c] + beta[c];
    atomicAdd(&out[batch[n]*H + c], v);
}

// ---------------- host orchestration ----------------
extern "C" void kernel_launch(void* const* d_in, const int* in_sizes, int n_in,
                              void* d_out, int out_size)
{
    const int*   atom_ids   = (const int*)  d_in[0];
    const int*   node_ids   = (const int*)  d_in[1];
    const int*   intra_ei   = (const int*)  d_in[2];
    const int*   intra_bond = (const int*)  d_in[3];
    const int*   edge_index = (const int*)  d_in[4];
    const int*   canon_bond = (const int*)  d_in[5];
    const int*   batch      = (const int*)  d_in[6];
    const float* log_probs  = (const float*)d_in[7];
    const float* atom_tab   = (const float*)d_in[8];
    const float* bond_tab   = (const float*)d_in[9];
    const float* dist_tab   = (const float*)d_in[10];
    const float* logp_W     = (const float*)d_in[11];
    const float* logp_b     = (const float*)d_in[12];
    const float* lw         = (const float*)d_in[13];
    const float* lb         = (const float*)d_in[14];
    const float* bn_g       = (const float*)d_in[15];
    const float* bn_b       = (const float*)d_in[16];
    const float* eps        = (const float*)d_in[17];
    const float* inW        = (const float*)d_in[18];
    const float* inB        = (const float*)d_in[19];
    const float* outW       = (const float*)d_in[20];
    const float* outB       = (const float*)d_in[21];
    const float* ro_g       = (const float*)d_in[22];
    const float* ro_b       = (const float*)d_in[23];
    float* out = (float*)d_out;

    cudaFuncSetAttribute(k_gemm_tc, cudaFuncAttributeMaxDynamicSharedMemorySize,
                         GEMM_SMEM_BYTES);

    float *p_h, *p_t1, *p_t2, *p_t3, *p_r, *p_h2, *p_o, *p_qkv, *p_hcan, *p_agg2,
          *p_c1, *p_c2, *p_stats, *p_stats2, *p_cnt, *p_linE0, *p_linE1;
    int *p_slotcnt;
    cudaGetSymbolAddress((void**)&p_h,    g_h);
    cudaGetSymbolAddress((void**)&p_t1,   g_t1);
    cudaGetSymbolAddress((void**)&p_t2,   g_t2);
    cudaGetSymbolAddress((void**)&p_t3,   g_t3);
    cudaGetSymbolAddress((void**)&p_r,    g_r);
    cudaGetSymbolAddress((void**)&p_h2,   g_h2);
    cudaGetSymbolAddress((void**)&p_o,    g_o);
    cudaGetSymbolAddress((void**)&p_qkv,  g_qkv);
    cudaGetSymbolAddress((void**)&p_hcan, g_hcan);
    cudaGetSymbolAddress((void**)&p_agg2, g_agg2);
    cudaGetSymbolAddress((void**)&p_c1,   g_c1);
    cudaGetSymbolAddress((void**)&p_c2,   g_c2);
    cudaGetSymbolAddress((void**)&p_stats, g_stats);
    cudaGetSymbolAddress((void**)&p_stats2,g_stats2);
    cudaGetSymbolAddress((void**)&p_cnt,  g_cnt);
    cudaGetSymbolAddress((void**)&p_linE0,g_linE0);
    cudaGetSymbolAddress((void**)&p_linE1,g_linE1);
    cudaGetSymbolAddress((void**)&p_slotcnt, g_slotcnt);

    const int* isrc = intra_ei;

    cudaMemsetAsync(p_cnt, 0, NT*sizeof(float));
    cudaMemsetAsync(p_slotcnt, 0, NT*sizeof(int));
    k_init<<<SKc*H/256, 256>>>(atom_ids, node_ids, log_probs, atom_tab, dist_tab, logp_W, logp_b);
    k_cntslot<<<Ss/256, 256>>>(node_ids);

    for (int l = 0; l < Lc; l++) {
        const float* W  = lw + (long)l*8*H*H;
        const float* bb = lb + (long)l*8*H;
        k_linE<<<4, 256>>>(bond_tab, W + 0*H*H, bb + 0*H, p_linE0);
        k_linE<<<4, 256>>>(bond_tab, W + 5*H*H, bb + 5*H, p_linE1);

        // intra GINE: t1 = (1+eps)h + agg ; t2 = relu(t1@W1+b1) ; t1 = t2@W2+b2
        k_hh_intra<<<SKc*H/256, 256>>>(isrc, intra_bond, eps + l*2);
        k_gemm_tc<<<SKc/128, 256, GEMM_SMEM_BYTES>>>(p_t1, 128, W + 1*H*H, bb + 1*H,
                                                     nullptr, 0, p_t2, 128, 1);
        k_gemm_tc<<<SKc/128, 256, GEMM_SMEM_BYTES>>>(p_t2, 128, W + 2*H*H, bb + 2*H,
                                                     nullptr, 0, p_t1, 128, 0);
        cudaMemsetAsync(p_stats, 0, 2*H*sizeof(float));
        k_bn_stats<<<SKc/512, 128>>>(p_t1, p_stats);

        // non-root path: t3 = h@W3+b3 ; r = h_root@W4+b4
        k_gemm_tc<<<SKc/128, 256, GEMM_SMEM_BYTES>>>(p_h, 128, W + 3*H*H, bb + 3*H,
                                                     nullptr, 0, p_t3, 128, 0);
        k_gemm_tc<<<Ss/128, 256, GEMM_SMEM_BYTES>>>(p_h, Kk*H, W + 4*H*H, bb + 4*H,
                                                    nullptr, 0, p_r, 128, 0);

        // canonical graph: c1 = GINE(hcan) ; c1 = mlp(c1) ; c2 = BN(c1)
        cudaMemsetAsync(p_hcan, 0, NT*H*sizeof(float));
        k_hcan_acc<<<Ss*H/256, 256>>>(node_ids);
        k_hcan_div<<<NT*H/256, 256>>>();
        cudaMemsetAsync(p_agg2, 0, NT*H*sizeof(float));
        k_cagg<<<ECc*H/256, 256>>>(edge_index, canon_bond);
        k_hh2<<<NT*H/256, 256>>>(eps + l*2 + 1);
        k_gemm_tc<<<NT/128, 256, GEMM_SMEM_BYTES>>>(p_c1, 128, W + 6*H*H, bb + 6*H,
                                                    nullptr, 0, p_c2, 128, 1);
        k_gemm_tc<<<NT/128, 256, GEMM_SMEM_BYTES>>>(p_c2, 128, W + 7*H*H, bb + 7*H,
                                                    nullptr, 0, p_c1, 128, 0);
        cudaMemsetAsync(p_stats2, 0, 2*H*sizeof(float));
        k_bn_stats<<<NT/512, 128>>>(p_c1, p_stats2);
        k_bn_apply<<<NT*H/256, 256>>>(p_c1, p_c2, p_stats2,
                                      bn_g + (l*2+1)*H, bn_b + (l*2+1)*H, 1.f/NT);

        // combine (big BN fused here from g_stats)
        k_combine<<<SKc*H/256, 256>>>(node_ids, bn_g + (l*2+0)*H, bn_b + (l*2+0)*H);
    }

    // pooling + attention + readout
    k_pool<<<Ss*H/256, 256>>>(node_ids);
    for (int cb = 0; cb < 3; cb++)
        k_gemm_tc<<<Ss/128, 256, GEMM_SMEM_BYTES>>>(p_h2, 128, inW + (long)cb*H*H, inB + cb*H,
                                                    nullptr, 0, p_qkv + cb*H, 384, 0);
    k_attn<<<NT*16/256, 256>>>();
    k_gemm_tc<<<Ss/128, 256, GEMM_SMEM_BYTES>>>(p_o, 128, outW, outB, p_h2, 128, p_r, 128, 0);
    k_mean4<<<NT*H/256, 256>>>();
    cudaMemsetAsync(p_stats, 0, 2*H*sizeof(float));
    k_bn_stats<<<NT/512, 128>>>(p_c1, p_stats);
    cudaMemsetAsync(d_out, 0, (size_t)out_size*sizeof(float));
    k_final<<<NT*H/256, 256>>>(batch, ro_g, ro_b, out);
}